// round 4
// baseline (speedup 1.0000x reference)
#include <cuda_runtime.h>
#include <math.h>

#define BB 8
#define NPTS 2048
#define KNB 32
#define MSEL 1024
#define CF 128
#define LRELU 0.2f
#define ATTN_SCALE 0.088388347648318447f

// ---------------- static device scratch ----------------
static __device__ float g_big[(size_t)BB*NPTS*NPTS];
static __device__ float g_h[(size_t)BB*256*NPTS];
static __device__ float g_hfull[(size_t)BB*CF*NPTS];
static __device__ float g_bq[(size_t)BB*CF*NPTS];
static __device__ float g_bk[(size_t)BB*CF*NPTS];
static __device__ float g_bv[(size_t)BB*CF*NPTS];
static __device__ float g_ba[(size_t)BB*CF*NPTS];
static __device__ float g_by[(size_t)BB*CF*NPTS];
static __device__ float g_f1[(size_t)BB*512*NPTS];
static __device__ float g_s1[(size_t)BB*CF*NPTS];
static __device__ float g_s2[(size_t)BB*CF*NPTS];
static __device__ float g_hd[(size_t)BB*CF*MSEL];
static __device__ float g_hu[(size_t)BB*CF*NPTS];
static __device__ float g_xtmp[(size_t)BB*CF*NPTS];
static __device__ float g_xh[(size_t)BB*1024*NPTS];
static __device__ float g_xc[(size_t)BB*1024*NPTS];
static __device__ float g_xc2[(size_t)BB*256*NPTS];
static __device__ float g_sqn[(size_t)BB*NPTS];
static __device__ float g_score[(size_t)BB*NPTS];
static __device__ float g_gv[(size_t)BB*2112];
static __device__ float g_bias[(size_t)BB*1024];
static __device__ float g_mu[1024];
static __device__ float g_rstd[1024];
static __device__ int   g_idx[(size_t)BB*NPTS*KNB];
static __device__ int   g_sel[(size_t)BB*MSEL];

// ---------------- generic strided batched GEMM ----------------
// O[bz*o_b + i*o_i + j] = sum_k A[bz*a_b + i*a_i + k*a_k] * B[bz*b_b + k*b_k + j*b_j]
__global__ void __launch_bounds__(256)
gemm_kernel(const float* __restrict__ A, const float* __restrict__ Bm,
            float* __restrict__ O, int I, int J, int Kd,
            long a_b, long a_i, long a_k,
            long b_b, long b_k, long b_j,
            long o_b, long o_i)
{
    __shared__ float As[16*65];
    __shared__ float Bs[16*65];
    int bz = blockIdx.z;
    const float* Ab = A + (long)bz*a_b;
    const float* Bb = Bm + (long)bz*b_b;
    int i0 = blockIdx.y*64, j0 = blockIdx.x*64;
    int tx = threadIdx.x, ty = threadIdx.y;
    int tid = ty*16 + tx;
    float acc[4][4] = {};
    for (int k0 = 0; k0 < Kd; k0 += 16) {
        #pragma unroll
        for (int r = 0; r < 4; r++) {
            int e = tid + r*256;
            int kk, ii;
            if (a_k == 1) { ii = e >> 4; kk = e & 15; } else { kk = e >> 6; ii = e & 63; }
            float v = 0.f;
            if (i0+ii < I && k0+kk < Kd) v = Ab[(long)(i0+ii)*a_i + (long)(k0+kk)*a_k];
            As[kk*65+ii] = v;
        }
        #pragma unroll
        for (int r = 0; r < 4; r++) {
            int e = tid + r*256;
            int kk, jj;
            if (b_j == 1) { kk = e >> 6; jj = e & 63; } else { jj = e >> 4; kk = e & 15; }
            float v = 0.f;
            if (j0+jj < J && k0+kk < Kd) v = Bb[(long)(k0+kk)*b_k + (long)(j0+jj)*b_j];
            Bs[kk*65+jj] = v;
        }
        __syncthreads();
        #pragma unroll
        for (int kk = 0; kk < 16; kk++) {
            float av[4], bv[4];
            #pragma unroll
            for (int u = 0; u < 4; u++) av[u] = As[kk*65 + ty*4 + u];
            #pragma unroll
            for (int v = 0; v < 4; v++) bv[v] = Bs[kk*65 + tx*4 + v];
            #pragma unroll
            for (int u = 0; u < 4; u++)
                #pragma unroll
                for (int v = 0; v < 4; v++) acc[u][v] += av[u]*bv[v];
        }
        __syncthreads();
    }
    #pragma unroll
    for (int u = 0; u < 4; u++) {
        int i = i0 + ty*4 + u;
        if (i >= I) continue;
        #pragma unroll
        for (int v = 0; v < 4; v++) {
            int j = j0 + tx*4 + v;
            if (j < J) O[(long)bz*o_b + (long)i*o_i + j] = acc[u][v];
        }
    }
}

static void gemm_launch(const float* A, const float* B, float* O,
                        int Bn, int I, int J, int Kd,
                        long a_b, long a_i, long a_k,
                        long b_b, long b_k, long b_j,
                        long o_b, long o_i)
{
    dim3 grid((J+63)/64, (I+63)/64, Bn);
    gemm_kernel<<<grid, dim3(16,16)>>>(A,B,O,I,J,Kd,a_b,a_i,a_k,b_b,b_k,b_j,o_b,o_i);
}
static void gemmW(const float* W, int Oc, int Kd, int rowlen,
                  const float* X, long xbs, int Np, float* O, long obs)
{
    gemm_launch(W, X, O, BB, Oc, Np, Kd, 0, rowlen, 1, xbs, Np, 1, obs, Np);
}
static void gemmTN(const float* X, long xbs, int Np,
                   const float* Y, long ybs, int Mp, int Cin, float* S)
{
    gemm_launch(X, Y, S, BB, Np, Mp, Cin, xbs, 1, Np, ybs, Mp, 1, (long)Np*Mp, Mp);
}

// ---------------- helper kernels ----------------
__global__ void sqnorm_kernel(const float* __restrict__ x, float* __restrict__ sq,
                              int Cin, int Np, long bstride)
{
    int b = blockIdx.y;
    int n = blockIdx.x*256 + threadIdx.x;
    if (n >= Np) return;
    const float* p = x + (long)b*bstride + n;
    float s = 0.f;
    for (int c = 0; c < Cin; c++) { float v = p[(long)c*Np]; s += v*v; }
    sq[(long)b*Np + n] = s;
}

__global__ void knn_topk_kernel(const float* __restrict__ inner, const float* __restrict__ sq,
                                int* __restrict__ idxout, int Np)
{
    __shared__ float d[NPTS];
    __shared__ float wv[8];
    __shared__ int   wi[8];
    int row = blockIdx.x;
    int b = row / Np, n = row % Np;
    int t = threadIdx.x, lane = t & 31, w = t >> 5;
    const float* ir = inner + ((size_t)b*Np + n)*Np;
    const float* sqb = sq + (size_t)b*Np;
    float sn = sqb[n];
    for (int m = t; m < Np; m += 256) d[m] = sn - 2.0f*ir[m] + sqb[m];
    __syncthreads();
    int* op = idxout + (size_t)row*KNB;
    for (int k = 0; k < KNB; k++) {
        float bv = 3.4e38f; int bi = 0x7fffffff;
        for (int m = t; m < Np; m += 256) {
            float v = d[m];
            if (v < bv || (v == bv && m < bi)) { bv = v; bi = m; }
        }
        #pragma unroll
        for (int o = 16; o; o >>= 1) {
            float ov = __shfl_down_sync(0xffffffffu, bv, o);
            int   oi = __shfl_down_sync(0xffffffffu, bi, o);
            if (ov < bv || (ov == bv && oi < bi)) { bv = ov; bi = oi; }
        }
        if (lane == 0) { wv[w] = bv; wi[w] = bi; }
        __syncthreads();
        if (t == 0) {
            for (int u = 1; u < 8; u++)
                if (wv[u] < bv || (wv[u] == bv && wi[u] < bi)) { bv = wv[u]; bi = wi[u]; }
            op[k] = bi; d[bi] = 3.4e38f;
        }
        __syncthreads();
    }
}

// v_k = A - Bm + Bm[idx_k]; max -> pre, sum/sumsq -> s1/s2
__global__ void edge_pass1_kernel(const float* __restrict__ A, const float* __restrict__ Bm,
                                  const int* __restrict__ idx, float* __restrict__ pre,
                                  float* __restrict__ s1, float* __restrict__ s2,
                                  int Np, long pre_bs)
{
    size_t i = (size_t)blockIdx.x*256 + threadIdx.x;
    if (i >= (size_t)BB*CF*Np) return;
    int n = (int)(i % Np); size_t tt = i / Np;
    int o = (int)(tt % CF); int b = (int)(tt / CF);
    size_t base = ((size_t)b*CF + o)*Np;
    float a = A[base+n], bm = Bm[base+n];
    float diff = a - bm;
    const int* ip = idx + ((size_t)b*Np + n)*KNB;
    const float* Br = Bm + base;
    float s = 0.f, ss = 0.f, mx = -3.4e38f;
    #pragma unroll 4
    for (int k = 0; k < KNB; k++) {
        float v = diff + Br[ip[k]];
        s += v; ss += v*v; mx = fmaxf(mx, v);
    }
    pre[(size_t)b*pre_bs + (size_t)o*Np + n] = mx;
    s1[i] = s; s2[i] = ss;
}

__global__ void bn_stats_kernel(const float* __restrict__ x, float* __restrict__ mu,
                                float* __restrict__ rstd, long bstride, int Np, double invcount)
{
    int o = blockIdx.x, t = threadIdx.x;
    double s = 0.0, ss = 0.0;
    for (int b = 0; b < BB; b++) {
        const float* p = x + (long)b*bstride + (long)o*Np;
        for (int n = t; n < Np; n += 256) { double v = p[n]; s += v; ss += v*v; }
    }
    __shared__ double sh1[256], sh2[256];
    sh1[t] = s; sh2[t] = ss; __syncthreads();
    for (int st = 128; st; st >>= 1) {
        if (t < st) { sh1[t] += sh1[t+st]; sh2[t] += sh2[t+st]; }
        __syncthreads();
    }
    if (!t) {
        double m = sh1[0]*invcount;
        double var = sh2[0]*invcount - m*m;
        mu[o] = (float)m;
        rstd[o] = (float)(1.0/sqrt(var + 1e-5));
    }
}

__global__ void bn_stats2_kernel(const float* __restrict__ s1, const float* __restrict__ s2,
                                 float* __restrict__ mu, float* __restrict__ rstd,
                                 long bstride, int Np, double invcount)
{
    int o = blockIdx.x, t = threadIdx.x;
    double s = 0.0, ss = 0.0;
    for (int b = 0; b < BB; b++) {
        const float* p1 = s1 + (long)b*bstride + (long)o*Np;
        const float* p2 = s2 + (long)b*bstride + (long)o*Np;
        for (int n = t; n < Np; n += 256) { s += (double)p1[n]; ss += (double)p2[n]; }
    }
    __shared__ double sh1[256], sh2[256];
    sh1[t] = s; sh2[t] = ss; __syncthreads();
    for (int st = 128; st; st >>= 1) {
        if (t < st) { sh1[t] += sh1[t+st]; sh2[t] += sh2[t+st]; }
        __syncthreads();
    }
    if (!t) {
        double m = sh1[0]*invcount;
        double var = sh2[0]*invcount - m*m;
        mu[o] = (float)m;
        rstd[o] = (float)(1.0/sqrt(var + 1e-5));
    }
}

__global__ void bn_apply_kernel(const float* __restrict__ x, const float* __restrict__ res,
                                float* __restrict__ out, const float* __restrict__ mu,
                                const float* __restrict__ rstd, size_t total,
                                int Np, int Cch, long bstride)
{
    size_t i = (size_t)blockIdx.x*256 + threadIdx.x;
    if (i >= total) return;
    int n = (int)(i % Np); size_t tt = i / Np;
    int o = (int)(tt % Cch); int b = (int)(tt / Cch);
    size_t off = (size_t)b*bstride + (size_t)o*Np + n;
    float v = (x[off] - mu[o]) * rstd[o];
    v = v >= 0.f ? v : LRELU*v;
    out[off] = (res ? res[off] : 0.f) + v;
}

__global__ void attn_kernel(const float* __restrict__ q, const float* __restrict__ Km,
                            const float* __restrict__ Vm, const int* __restrict__ idx,
                            float* __restrict__ out, int Np)
{
    int bn = blockIdx.x;
    int b = bn / Np, n = bn % Np;
    int t = threadIdx.x, w = t >> 5, lane = t & 31;
    size_t base = (size_t)b*CF*Np;
    __shared__ int   sidx[KNB];
    __shared__ float part[4][KNB];
    __shared__ float aw[KNB];
    if (t < KNB) sidx[t] = idx[(size_t)bn*KNB + t];
    __syncthreads();
    float qc = q[base + (size_t)t*Np + n];
    const float* Kb = Km + base + (size_t)t*Np;
    for (int k = 0; k < KNB; k++) {
        float v = qc * Kb[sidx[k]];
        #pragma unroll
        for (int o = 16; o; o >>= 1) v += __shfl_down_sync(0xffffffffu, v, o);
        if (lane == 0) part[w][k] = v;
    }
    __syncthreads();
    if (w == 0) {
        float l = (part[0][lane] + part[1][lane] + part[2][lane] + part[3][lane]) * ATTN_SCALE;
        float m = l;
        #pragma unroll
        for (int o = 16; o; o >>= 1) m = fmaxf(m, __shfl_xor_sync(0xffffffffu, m, o));
        float e = expf(l - m);
        float s = e;
        #pragma unroll
        for (int o = 16; o; o >>= 1) s += __shfl_xor_sync(0xffffffffu, s, o);
        aw[lane] = e / s;
    }
    __syncthreads();
    const float* Vb = Vm + base + (size_t)t*Np;
    float acc = 0.f;
    for (int k = 0; k < KNB; k++) acc += aw[k]*Vb[sidx[k]];
    out[base + (size_t)t*Np + n] = acc;
}

__global__ void softmax_kernel(float* __restrict__ S, int M, float scale)
{
    __shared__ float sh[NPTS];
    __shared__ float red[256];
    size_t row = blockIdx.x;
    float* r = S + row*(size_t)M;
    int t = threadIdx.x;
    float mx = -3.4e38f;
    for (int i = t; i < M; i += 256) { float v = r[i]*scale; sh[i] = v; mx = fmaxf(mx, v); }
    red[t] = mx; __syncthreads();
    for (int s = 128; s; s >>= 1) { if (t < s) red[t] = fmaxf(red[t], red[t+s]); __syncthreads(); }
    mx = red[0]; __syncthreads();
    float sum = 0.f;
    for (int i = t; i < M; i += 256) { float e = expf(sh[i] - mx); sh[i] = e; sum += e; }
    red[t] = sum; __syncthreads();
    for (int s = 128; s; s >>= 1) { if (t < s) red[t] += red[t+s]; __syncthreads(); }
    float inv = 1.0f/red[0];
    for (int i = t; i < M; i += 256) r[i] = sh[i]*inv;
}

__global__ void colmean_kernel(const float* __restrict__ S, float* __restrict__ score, int R, int M)
{
    int b = blockIdx.y;
    int m = blockIdx.x*256 + threadIdx.x;
    if (m >= M) return;
    const float* p = S + (size_t)b*R*M + m;
    float s = 0.f;
    for (int n = 0; n < R; n++) s += p[(size_t)n*M];
    score[(size_t)b*M + m] = s / (float)R;
}

__global__ void topm_kernel(const float* __restrict__ score, int* __restrict__ sel)
{
    __shared__ float v[NPTS];
    __shared__ int   id[NPTS];
    int b = blockIdx.x, t = threadIdx.x;
    for (int i = t; i < NPTS; i += 1024) { v[i] = score[(size_t)b*NPTS + i]; id[i] = i; }
    __syncthreads();
    for (int k = 2; k <= NPTS; k <<= 1) {
        for (int j = k >> 1; j > 0; j >>= 1) {
            for (int i = t; i < NPTS; i += 1024) {
                int p = i ^ j;
                if (p > i) {
                    bool up = ((i & k) == 0);   // descending region
                    float vi = v[i], vp = v[p]; int ii = id[i], ip = id[p];
                    bool inOrder = (vi > vp) || (vi == vp && ii < ip);
                    if (up ? !inOrder : inOrder) { v[i]=vp; v[p]=vi; id[i]=ip; id[p]=ii; }
                }
            }
            __syncthreads();
        }
    }
    for (int i = t; i < MSEL; i += 1024) sel[(size_t)b*MSEL + i] = id[i];
}

__global__ void gather_kernel(const float* __restrict__ x, const int* __restrict__ sel,
                              float* __restrict__ out, int Np, int Ms)
{
    size_t i = (size_t)blockIdx.x*256 + threadIdx.x;
    if (i >= (size_t)BB*CF*Ms) return;
    int j = (int)(i % Ms); size_t tt = i / Ms;
    int c = (int)(tt % CF); int b = (int)(tt / CF);
    out[i] = x[((size_t)b*CF + c)*Np + sel[(size_t)b*Ms + j]];
}

__global__ void add_kernel(const float* __restrict__ a, const float* __restrict__ b,
                           float* __restrict__ o, size_t total)
{
    size_t i = (size_t)blockIdx.x*256 + threadIdx.x;
    if (i < total) o[i] = a[i] + b[i];
}

__global__ void maxmean_kernel(const float* __restrict__ xh, float* __restrict__ g, int Np)
{
    __shared__ float rm[256], rs[256];
    int bo = blockIdx.x;
    int b = bo >> 10, o = bo & 1023;
    const float* p = xh + ((size_t)b*1024 + o)*Np;
    int t = threadIdx.x;
    float mx = -3.4e38f, s = 0.f;
    for (int n = t; n < Np; n += 256) { float v = p[n]; mx = fmaxf(mx, v); s += v; }
    rm[t] = mx; rs[t] = s; __syncthreads();
    for (int st = 128; st; st >>= 1) {
        if (t < st) { rm[t] = fmaxf(rm[t], rm[t+st]); rs[t] += rs[t+st]; }
        __syncthreads();
    }
    if (!t) { g[(size_t)b*2112 + o] = rm[0]; g[(size_t)b*2112 + 1024 + o] = rs[0]/(float)Np; }
}

__global__ void cid_kernel(const float* __restrict__ cat, const float* __restrict__ Wc1,
                           float* __restrict__ g)
{
    int o = threadIdx.x;   // 64
    float y[BB];
    for (int b = 0; b < BB; b++) {
        float s = 0.f;
        for (int c = 0; c < 16; c++) s += Wc1[o*16+c]*cat[b*16+c];
        y[b] = s;
    }
    float mu = 0.f;
    for (int b = 0; b < BB; b++) mu += y[b];
    mu *= (1.0f/BB);
    float var = 0.f;
    for (int b = 0; b < BB; b++) { float dd = y[b]-mu; var += dd*dd; }
    var *= (1.0f/BB);
    float rs = rsqrtf(var + 1e-5f);
    for (int b = 0; b < BB; b++) {
        float v = (y[b]-mu)*rs;
        g[(size_t)b*2112 + 2048 + o] = v >= 0.f ? v : LRELU*v;
    }
}

__global__ void bias_kernel(const float* __restrict__ W, const float* __restrict__ g,
                            float* __restrict__ bias)
{
    int gw = blockIdx.x*8 + (threadIdx.x >> 5);
    if (gw >= BB*1024) return;
    int lane = threadIdx.x & 31;
    int b = gw >> 10, o = gw & 1023;
    const float* wr = W + (size_t)o*2240;
    const float* gb = g + (size_t)b*2112;
    float s = 0.f;
    for (int c = lane; c < 2112; c += 32) s += wr[c]*gb[c];
    #pragma unroll
    for (int off = 16; off; off >>= 1) s += __shfl_down_sync(0xffffffffu, s, off);
    if (!lane) bias[(size_t)b*1024 + o] = s;
}

__global__ void addbias_kernel(float* __restrict__ xc, const float* __restrict__ bias)
{
    size_t i = (size_t)blockIdx.x*256 + threadIdx.x;
    if (i >= (size_t)BB*1024*NPTS) return;
    size_t tt = i / NPTS;
    int o = (int)(tt % 1024); int b = (int)(tt / 1024);
    xc[i] += bias[(size_t)b*1024 + o];
}

// ---------------- host orchestration ----------------
struct Bufs {
    float *big,*h,*hfull,*bq,*bk,*bv,*ba,*by,*f1,*s1,*s2,*hd,*hu,*xtmp,*xh,*xc,*xc2;
    float *sq,*score,*gv,*bias,*mu,*rstd;
    int *idx,*sel;
};

static void getbufs(Bufs& P)
{
    cudaGetSymbolAddress((void**)&P.big, g_big);
    cudaGetSymbolAddress((void**)&P.h, g_h);
    cudaGetSymbolAddress((void**)&P.hfull, g_hfull);
    cudaGetSymbolAddress((void**)&P.bq, g_bq);
    cudaGetSymbolAddress((void**)&P.bk, g_bk);
    cudaGetSymbolAddress((void**)&P.bv, g_bv);
    cudaGetSymbolAddress((void**)&P.ba, g_ba);
    cudaGetSymbolAddress((void**)&P.by, g_by);
    cudaGetSymbolAddress((void**)&P.f1, g_f1);
    cudaGetSymbolAddress((void**)&P.s1, g_s1);
    cudaGetSymbolAddress((void**)&P.s2, g_s2);
    cudaGetSymbolAddress((void**)&P.hd, g_hd);
    cudaGetSymbolAddress((void**)&P.hu, g_hu);
    cudaGetSymbolAddress((void**)&P.xtmp, g_xtmp);
    cudaGetSymbolAddress((void**)&P.xh, g_xh);
    cudaGetSymbolAddress((void**)&P.xc, g_xc);
    cudaGetSymbolAddress((void**)&P.xc2, g_xc2);
    cudaGetSymbolAddress((void**)&P.sq, g_sqn);
    cudaGetSymbolAddress((void**)&P.score, g_score);
    cudaGetSymbolAddress((void**)&P.gv, g_gv);
    cudaGetSymbolAddress((void**)&P.bias, g_bias);
    cudaGetSymbolAddress((void**)&P.mu, g_mu);
    cudaGetSymbolAddress((void**)&P.rstd, g_rstd);
    cudaGetSymbolAddress((void**)&P.idx, g_idx);
    cudaGetSymbolAddress((void**)&P.sel, g_sel);
}

static inline size_t cdiv(size_t a, size_t b) { return (a + b - 1)/b; }

static void run_bn(float* x, const float* res, float* out, int Cch, int Np, long bstride, Bufs& P)
{
    bn_stats_kernel<<<Cch, 256>>>(x, P.mu, P.rstd, bstride, Np, 1.0/((double)BB*Np));
    size_t total = (size_t)BB*Cch*Np;
    bn_apply_kernel<<<(unsigned)cdiv(total,256), 256>>>(x, res, out, P.mu, P.rstd, total, Np, Cch, bstride);
}

static void run_knn(const float* xin, long xbs, int cin, int Np, Bufs& P)
{
    dim3 gs((Np+255)/256, BB);
    sqnorm_kernel<<<gs, 256>>>(xin, P.sq, cin, Np, xbs);
    gemmTN(xin, xbs, Np, xin, xbs, Np, cin, P.big);
    knn_topk_kernel<<<BB*Np, 256>>>(P.big, P.sq, P.idx, Np);
}

static void run_edge(const float* xin, long xbs, int cin, const float* W, int rowlen,
                     float* outslice, long out_bs, Bufs& P)
{
    run_knn(xin, xbs, cin, NPTS, P);
    gemmW(W,       CF, cin, rowlen, xin, xbs, NPTS, P.bq, (long)CF*NPTS);
    gemmW(W + cin, CF, cin, rowlen, xin, xbs, NPTS, P.bk, (long)CF*NPTS);
    size_t total = (size_t)BB*CF*NPTS;
    edge_pass1_kernel<<<(unsigned)cdiv(total,256), 256>>>(P.bq, P.bk, P.idx, outslice, P.s1, P.s2, NPTS, out_bs);
    bn_stats2_kernel<<<CF, 256>>>(P.s1, P.s2, P.mu, P.rstd, (long)CF*NPTS, NPTS,
                                  1.0/((double)BB*NPTS*KNB));
    bn_apply_kernel<<<(unsigned)cdiv(total,256), 256>>>(outslice, nullptr, outslice, P.mu, P.rstd,
                                                        total, NPTS, CF, out_bs);
}

static void run_n2p(const float* xin, long xbs, int cin, int Np,
                    const float* Wq, const float* Wk, const float* Wv, const float* Wo,
                    const float* Wf1, const float* Wf2, float* outp, Bufs& P)
{
    run_knn(xin, xbs, cin, Np, P);
    long fbs = (long)CF*Np;
    gemmW(Wq, CF, cin, cin, xin, xbs, Np, P.bq, fbs);
    gemmW(Wk, CF, cin, cin, xin, xbs, Np, P.bk, fbs);
    gemmW(Wv, CF, cin, cin, xin, xbs, Np, P.bv, fbs);
    attn_kernel<<<BB*Np, 128>>>(P.bq, P.bk, P.bv, P.idx, P.ba, Np);
    gemmW(Wo, CF, CF, CF, P.ba, fbs, Np, P.by, fbs);
    run_bn(P.by, nullptr, P.by, CF, Np, fbs, P);
    long f1bs = 512L*Np;
    gemmW(Wf1, 512, CF, CF, P.by, fbs, Np, P.f1, f1bs);
    run_bn(P.f1, nullptr, P.f1, 512, Np, f1bs, P);
    gemmW(Wf2, CF, 512, 512, P.f1, f1bs, Np, P.bq, fbs);
    bn_stats_kernel<<<CF, 256>>>(P.bq, P.mu, P.rstd, fbs, Np, 1.0/((double)BB*Np));
    size_t total = (size_t)BB*CF*Np;
    bn_apply_kernel<<<(unsigned)cdiv(total,256), 256>>>(P.bq, P.by, outp, P.mu, P.rstd,
                                                        total, Np, CF, fbs);
}

extern "C" void kernel_launch(void* const* d_in, const int* in_sizes, int n_in,
                              void* d_out, int out_size)
{
    const float* x    = (const float*)d_in[0];
    const float* cat  = (const float*)d_in[1];
    const float* We0  = (const float*)d_in[2];
    const float* We1  = (const float*)d_in[3];
    const float *Wq[3], *Wk[3], *Wv[3], *Wo[3], *Wf1[3], *Wf2[3];
    for (int l = 0; l < 3; l++) {
        Wq[l]  = (const float*)d_in[4 + 6*l];
        Wk[l]  = (const float*)d_in[5 + 6*l];
        Wv[l]  = (const float*)d_in[6 + 6*l];
        Wo[l]  = (const float*)d_in[7 + 6*l];
        Wf1[l] = (const float*)d_in[8 + 6*l];
        Wf2[l] = (const float*)d_in[9 + 6*l];
    }
    const float* Wdq = (const float*)d_in[22];
    const float* Wdk = (const float*)d_in[23];
    const float* Wuq = (const float*)d_in[24];
    const float* Wuk = (const float*)d_in[25];
    const float* Wuv = (const float*)d_in[26];
    const float* Wc  = (const float*)d_in[27];
    const float* Wc1 = (const float*)d_in[28];
    const float* Wc2 = (const float*)d_in[29];
    const float* Wc3 = (const float*)d_in[30];
    const float* Wc4 = (const float*)d_in[31];

    Bufs P; getbufs(P);
    const long HBS = 256L*NPTS;
    const long FBS = (long)CF*NPTS;

    // e0, e1 edge convs into concat buffer g_h
    run_edge(x,   3L*NPTS, 3,   We0, 6,   P.h,               HBS, P);
    run_edge(P.h, HBS,     128, We1, 256, P.h + 128L*NPTS,   HBS, P);

    // h_full = n2p_attn(concat)
    run_n2p(P.h, HBS, 256, NPTS, Wq[0], Wk[0], Wv[0], Wo[0], Wf1[0], Wf2[0], P.hfull, P);

    // down_global: select top-M columns by mean attention score
    gemmW(Wdq, CF, CF, CF, P.hfull, FBS, NPTS, P.bq, FBS);
    gemmW(Wdk, CF, CF, CF, P.hfull, FBS, NPTS, P.bk, FBS);
    gemmTN(P.bq, FBS, NPTS, P.bk, FBS, NPTS, CF, P.big);
    softmax_kernel<<<BB*NPTS, 256>>>(P.big, NPTS, ATTN_SCALE);
    {
        dim3 gs((NPTS+255)/256, BB);
        colmean_kernel<<<gs, 256>>>(P.big, P.score, NPTS, NPTS);
    }
    topm_kernel<<<BB, 1024>>>(P.score, P.sel);
    {
        size_t total = (size_t)BB*CF*MSEL;
        gather_kernel<<<(unsigned)cdiv(total,256), 256>>>(P.hfull, P.sel, P.hd, NPTS, MSEL);
    }

    // hd = n2p_attn(hd) on M=1024 points (in-place safe: input only read up front)
    run_n2p(P.hd, (long)CF*MSEL, CF, MSEL, Wq[1], Wk[1], Wv[1], Wo[1], Wf1[1], Wf2[1], P.hd, P);

    // up_cross: hu = h_full + softmax(q k^T / sqrt(C)) v
    gemmW(Wuq, CF, CF, CF, P.hfull, FBS, NPTS, P.bq, FBS);
    gemmW(Wuk, CF, CF, CF, P.hd, (long)CF*MSEL, MSEL, P.bk, (long)CF*MSEL);
    gemmW(Wuv, CF, CF, CF, P.hd, (long)CF*MSEL, MSEL, P.bv, (long)CF*MSEL);
    gemmTN(P.bq, FBS, NPTS, P.bk, (long)CF*MSEL, MSEL, CF, P.big);   // (B,N,M)
    softmax_kernel<<<BB*NPTS, 256>>>(P.big, MSEL, ATTN_SCALE);
    // out[b,c,n] = sum_m v[b,c,m] * a[b,n,m]
    gemm_launch(P.bv, P.big, P.hu, BB, CF, NPTS, MSEL,
                (long)CF*MSEL, MSEL, 1,
                (long)NPTS*MSEL, 1, MSEL,
                FBS, NPTS);
    {
        size_t total = (size_t)BB*CF*NPTS;
        add_kernel<<<(unsigned)cdiv(total,256), 256>>>(P.hfull, P.hu, P.hu, total);
    }

    // x_tmp = n2p_attn(hu)
    run_n2p(P.hu, FBS, CF, NPTS, Wq[2], Wk[2], Wv[2], Wo[2], Wf1[2], Wf2[2], P.xtmp, P);

    // xh = leaky(bn(Wc @ x_tmp))   (1024 ch)
    gemmW(Wc, 1024, CF, CF, P.xtmp, FBS, NPTS, P.xh, 1024L*NPTS);
    run_bn(P.xh, nullptr, P.xh, 1024, NPTS, 1024L*NPTS, P);

    // g vector: [max | mean | cid]
    maxmean_kernel<<<BB*1024, 256>>>(P.xh, P.gv, NPTS);
    cid_kernel<<<1, 64>>>(cat, Wc1, P.gv);
    bias_kernel<<<1024, 256>>>(Wc2, P.gv, P.bias);

    // xc = leaky(bn(Wc2[:,2112:] @ x_tmp + bias))
    gemmW(Wc2 + 2112, 1024, CF, 2240, P.xtmp, FBS, NPTS, P.xc, 1024L*NPTS);
    {
        size_t total = (size_t)BB*1024*NPTS;
        addbias_kernel<<<(unsigned)cdiv(total,256), 256>>>(P.xc, P.bias);
    }
    run_bn(P.xc, nullptr, P.xc, 1024, NPTS, 1024L*NPTS, P);

    // xc2 = leaky(bn(Wc3 @ xc))
    gemmW(Wc3, 256, 1024, 1024, P.xc, 1024L*NPTS, NPTS, P.xc2, 256L*NPTS);
    run_bn(P.xc2, nullptr, P.xc2, 256, NPTS, 256L*NPTS, P);

    // out = Wc4 @ xc2
    gemmW(Wc4, 50, 256, 256, P.xc2, 256L*NPTS, NPTS, (float*)d_out, 50L*NPTS);

    (void)in_sizes; (void)n_in; (void)out_size;
}